// round 8
// baseline (speedup 1.0000x reference)
#include <cuda_runtime.h>
#include <cuda_fp16.h>
#include <cstdint>

#define K_DIM 1024
#define N_DIM 1024
#define M_DIM 65536
#define BM 128
#define BN 256
#define BK 64
#define KSTAGES (K_DIM / BK)        // 16
#define PIPE 4
#define THREADS 320                  // 8 consumer warps + 2 producer warps
#define CONS_THREADS 256
#define GRID 152                     // persistent: 1 CTA/SM (GB300)
#define NTILES ((M_DIM / BM) * (N_DIM / BN))   // 2048
#define PITCH 144                    // 128B data + 16B pad (conflict-free ldmatrix)
#define A_OFF 0
#define A_BYTES (BM * PITCH)         // 18432
#define B_OFF A_BYTES
#define B_BYTES (BN * PITCH)         // 36864
#define STAGE_BYTES (A_BYTES + B_BYTES)   // 55296
#define MBAR_OFF (PIPE * STAGE_BYTES)     // 221184
#define SMEM_TOTAL (MBAR_OFF + 128)

// ---- device-global scratch (allocation-free) ----
__device__ float g_partial[1024];
__device__ float g_scale;
__device__ __align__(256) __half g_wq[N_DIM * K_DIM];   // ternary W, fp16

__device__ __forceinline__ uint32_t smem_u32(const void* p) {
    uint32_t a;
    asm("{ .reg .u64 t; cvta.to.shared.u64 t, %1; cvt.u32.u64 %0, t; }"
        : "=r"(a) : "l"(p));
    return a;
}
__device__ __forceinline__ void cp16(uint32_t dst, const void* src) {
    asm volatile("cp.async.cg.shared.global [%0], [%1], 16;" :: "r"(dst), "l"(src));
}
__device__ __forceinline__ void mbar_init(uint32_t bar, uint32_t cnt) {
    asm volatile("mbarrier.init.shared.b64 [%0], %1;" :: "r"(bar), "r"(cnt) : "memory");
}
__device__ __forceinline__ void mbar_arrive(uint32_t bar) {
    asm volatile("mbarrier.arrive.release.cta.shared.b64 _, [%0];" :: "r"(bar) : "memory");
}
__device__ __forceinline__ void cp_arrive_noinc(uint32_t bar) {
    asm volatile("cp.async.mbarrier.arrive.noinc.shared.b64 [%0];" :: "r"(bar) : "memory");
}
__device__ __forceinline__ void wait_parity(uint32_t bar, uint32_t phase) {
    asm volatile(
        "{\n\t.reg .pred P;\n"
        "W_%=:\n\t"
        "mbarrier.try_wait.parity.acquire.cta.shared::cta.b64 P, [%0], %1, 0x989680;\n\t"
        "@P bra.uni D_%=;\n\t"
        "bra.uni W_%=;\n\t"
        "D_%=:\n\t}"
        :: "r"(bar), "r"(phase) : "memory");
}
__device__ __forceinline__ void ldsm_x4(uint32_t* r, uint32_t addr) {
    asm volatile("ldmatrix.sync.aligned.m8n8.x4.shared.b16 {%0,%1,%2,%3}, [%4];"
                 : "=r"(r[0]), "=r"(r[1]), "=r"(r[2]), "=r"(r[3]) : "r"(addr));
}
__device__ __forceinline__ void mma16816(float* c, const uint32_t* a, uint32_t b0, uint32_t b1) {
    asm volatile(
        "mma.sync.aligned.m16n8k16.row.col.f32.f16.f16.f32 "
        "{%0,%1,%2,%3}, {%4,%5,%6,%7}, {%8,%9}, {%0,%1,%2,%3};"
        : "+f"(c[0]), "+f"(c[1]), "+f"(c[2]), "+f"(c[3])
        : "r"(a[0]), "r"(a[1]), "r"(a[2]), "r"(a[3]), "r"(b0), "r"(b1));
}

// ============================ pre-kernels ============================

__global__ void k_absmean(const float* __restrict__ w) {
    __shared__ float red[256];
    int t = threadIdx.x;
    float4 v = *(const float4*)(w + (size_t)blockIdx.x * 1024 + t * 4);
    red[t] = fabsf(v.x) + fabsf(v.y) + fabsf(v.z) + fabsf(v.w);
    __syncthreads();
    for (int o = 128; o > 0; o >>= 1) {
        if (t < o) red[t] += red[t + o];
        __syncthreads();
    }
    if (t == 0) g_partial[blockIdx.x] = red[0];
}

__global__ void k_scale() {
    __shared__ float red[256];
    int t = threadIdx.x;
    red[t] = g_partial[t] + g_partial[t + 256] + g_partial[t + 512] + g_partial[t + 768];
    __syncthreads();
    for (int o = 128; o > 0; o >>= 1) {
        if (t < o) red[t] += red[t + o];
        __syncthreads();
    }
    if (t == 0) g_scale = fmaxf(red[0] / 1048576.0f, 1e-5f);
}

__global__ void k_quant(const float* __restrict__ w) {
    int i = (blockIdx.x * 256 + threadIdx.x) * 4;
    float s = g_scale;
    float4 v = *(const float4*)(w + i);
    float q0 = fminf(fmaxf(rintf(v.x / s), -1.0f), 1.0f);
    float q1 = fminf(fmaxf(rintf(v.y / s), -1.0f), 1.0f);
    float q2 = fminf(fmaxf(rintf(v.z / s), -1.0f), 1.0f);
    float q3 = fminf(fmaxf(rintf(v.w / s), -1.0f), 1.0f);
    __half2 h0 = __floats2half2_rn(q0, q1);
    __half2 h1 = __floats2half2_rn(q2, q3);
    uint2 u;
    u.x = *reinterpret_cast<uint32_t*>(&h0);
    u.y = *reinterpret_cast<uint32_t*>(&h1);
    *(uint2*)(g_wq + i) = u;
}

// ====== GEMM: persistent, warp-specialized, producer converts X fp32->fp16 ===

__global__ void __launch_bounds__(THREADS, 1)
bitlinear_gemm(const float* __restrict__ x, float* __restrict__ out) {
    extern __shared__ __align__(128) char smem[];
    uint32_t sb = smem_u32(smem);
    int tid = threadIdx.x, lane = tid & 31, wid = tid >> 5;
    int bid = blockIdx.x;

    uint32_t full0  = sb + MBAR_OFF;
    uint32_t empty0 = sb + MBAR_OFF + PIPE * 8;
    if (tid == 0) {
        #pragma unroll
        for (int i = 0; i < PIPE; i++) {
            mbar_init(full0 + i * 8, 128);     // 64 threads x (1 noinc + 1 STS arrive)
            mbar_init(empty0 + i * 8, 256);    // 256 consumer threads
        }
    }
    __syncthreads();

    if (wid >= 8) {
        // ============ PRODUCER (2 warps, 64 threads): A = LDG+cvt+STS, B = cp.async
        int ptid = tid - CONS_THREADS;           // 0..63
        // A mapping: 4 threads/row-segment: prow 0..15, pseg 0..3 (16 floats each)
        int prow = ptid >> 2, pseg = ptid & 3;
        uint32_t adst0 = sb + A_OFF + prow * PITCH + pseg * 32;   // fp16 dest, 32B per seg
        // B mapping: 8 threads/row: brow 0..7, bcol 0..7 (16B each)
        int brow = ptid >> 3, bcol = ptid & 7;
        uint32_t bdst0 = sb + B_OFF + brow * PITCH + bcol * 16;

        int pb = 0, pph = 1;
        #pragma unroll 1
        for (int t = bid; t < NTILES; t += GRID) {
            int m0 = (t >> 2) * BM, n0 = (t & 3) * BN;
            const float*  abase = x + (size_t)(m0 + prow) * K_DIM + pseg * 16;
            const __half* bbase = g_wq + (size_t)(n0 + brow) * K_DIM + bcol * 8;
            #pragma unroll 1
            for (int s = 0; s < KSTAGES; s++) {
                wait_parity(empty0 + pb * 8, pph);
                uint32_t ab = pb * STAGE_BYTES;
                int k0 = s * BK;

                #pragma unroll
                for (int g = 0; g < 2; g++) {
                    // A loads: passes g*4 .. g*4+3 (rows prow + pass*16)
                    float4 v[16];
                    #pragma unroll
                    for (int p = 0; p < 4; p++) {
                        const float* src = abase + (size_t)(g * 64 + p * 16) * K_DIM + k0;
                        #pragma unroll
                        for (int j = 0; j < 4; j++) v[p * 4 + j] = *(const float4*)(src + j * 4);
                    }
                    // B cp.async: 16 rows (rows g*128 + brow + i*8)
                    #pragma unroll
                    for (int i = 0; i < 16; i++) {
                        int ro = g * 128 + i * 8;
                        cp16(bdst0 + ab + ro * PITCH,
                             bbase + (size_t)ro * K_DIM + k0);
                    }
                    // convert + STS
                    #pragma unroll
                    for (int p = 0; p < 4; p++) {
                        uint4 u0, u1;
                        __half2 h;
                        h = __floats2half2_rn(v[p*4+0].x, v[p*4+0].y); u0.x = *(uint32_t*)&h;
                        h = __floats2half2_rn(v[p*4+0].z, v[p*4+0].w); u0.y = *(uint32_t*)&h;
                        h = __floats2half2_rn(v[p*4+1].x, v[p*4+1].y); u0.z = *(uint32_t*)&h;
                        h = __floats2half2_rn(v[p*4+1].z, v[p*4+1].w); u0.w = *(uint32_t*)&h;
                        h = __floats2half2_rn(v[p*4+2].x, v[p*4+2].y); u1.x = *(uint32_t*)&h;
                        h = __floats2half2_rn(v[p*4+2].z, v[p*4+2].w); u1.y = *(uint32_t*)&h;
                        h = __floats2half2_rn(v[p*4+3].x, v[p*4+3].y); u1.z = *(uint32_t*)&h;
                        h = __floats2half2_rn(v[p*4+3].z, v[p*4+3].w); u1.w = *(uint32_t*)&h;
                        uint32_t d = adst0 + ab + (g * 64 + p * 16) * PITCH;
                        *(uint4*)(smem + (d - sb)) = u0;
                        *(uint4*)(smem + (d - sb) + 16) = u1;
                    }
                }
                cp_arrive_noinc(full0 + pb * 8);   // B complete
                mbar_arrive(full0 + pb * 8);       // A STS visible (release)
                if (++pb == PIPE) { pb = 0; pph ^= 1; }
            }
        }
    } else {
        // ======================= CONSUMER (8 warps) — unchanged ===============
        int wm = wid & 1, wn = wid >> 1;
        uint32_t a_ld[4], b_ld[4];
        #pragma unroll
        for (int mt = 0; mt < 4; mt++)
            a_ld[mt] = sb + A_OFF + (wm * 64 + mt * 16 + (lane & 15)) * PITCH
                     + (lane >> 4) * 16;
        #pragma unroll
        for (int np = 0; np < 4; np++)
            b_ld[np] = sb + B_OFF
                     + (wn * 64 + np * 16 + (lane & 7) + ((lane >> 4) & 1) * 8) * PITCH
                     + ((lane >> 3) & 1) * 16;

        float acc[4][8][4];
        #pragma unroll
        for (int i = 0; i < 4; i++)
            #pragma unroll
            for (int j = 0; j < 8; j++)
                #pragma unroll
                for (int k = 0; k < 4; k++) acc[i][j][k] = 0.0f;

        float sc = g_scale;
        int cb = 0, cph = 0;
        #pragma unroll 1
        for (int t = bid; t < NTILES; t += GRID) {
            #pragma unroll 1
            for (int s = 0; s < KSTAGES; s++) {
                wait_parity(full0 + cb * 8, cph);
                uint32_t ab = cb * STAGE_BYTES;
                #pragma unroll
                for (int ks = 0; ks < 4; ks++) {
                    uint32_t a[4][4], b[4][4];
                    #pragma unroll
                    for (int mt = 0; mt < 4; mt++)
                        ldsm_x4(a[mt], a_ld[mt] + ab + ks * 32);
                    #pragma unroll
                    for (int np = 0; np < 4; np++)
                        ldsm_x4(b[np], b_ld[np] + ab + ks * 32);
                    #pragma unroll
                    for (int np = 0; np < 4; np++) {
                        #pragma unroll
                        for (int mt = 0; mt < 4; mt++) {
                            mma16816(acc[mt][2 * np],     a[mt], b[np][0], b[np][1]);
                            mma16816(acc[mt][2 * np + 1], a[mt], b[np][2], b[np][3]);
                        }
                    }
                }
                mbar_arrive(empty0 + cb * 8);
                if (++cb == PIPE) { cb = 0; cph ^= 1; }
            }

            int m0 = (t >> 2) * BM, n0 = (t & 3) * BN;
            int row_base = m0 + wm * 64 + (lane >> 2);
            int col_base = n0 + wn * 64 + (lane & 3) * 2;
            #pragma unroll
            for (int mt = 0; mt < 4; mt++) {
                #pragma unroll
                for (int nt = 0; nt < 8; nt++) {
                    float2 v0, v1;
                    v0.x = acc[mt][nt][0] * sc; v0.y = acc[mt][nt][1] * sc;
                    v1.x = acc[mt][nt][2] * sc; v1.y = acc[mt][nt][3] * sc;
                    acc[mt][nt][0] = 0.0f; acc[mt][nt][1] = 0.0f;
                    acc[mt][nt][2] = 0.0f; acc[mt][nt][3] = 0.0f;
                    size_t r0 = (size_t)(row_base + mt * 16) * N_DIM + col_base + nt * 8;
                    size_t r1 = r0 + 8 * N_DIM;
                    *(float2*)(out + r0) = v0;
                    *(float2*)(out + r1) = v1;
                }
            }
        }
    }
}

// ============================ launch ============================

extern "C" void kernel_launch(void* const* d_in, const int* in_sizes, int n_in,
                              void* d_out, int out_size) {
    const float* x = (const float*)d_in[0];
    const float* w = (const float*)d_in[1];
    float* out = (float*)d_out;

    cudaFuncSetAttribute(bitlinear_gemm,
                         cudaFuncAttributeMaxDynamicSharedMemorySize, SMEM_TOTAL);

    k_absmean<<<1024, 256>>>(w);
    k_scale<<<1, 256>>>();
    k_quant<<<1024, 256>>>(w);

    bitlinear_gemm<<<GRID, THREADS, SMEM_TOTAL>>>(x, out);
}

// round 9
// speedup vs baseline: 1.0342x; 1.0342x over previous
#include <cuda_runtime.h>
#include <cuda_fp16.h>
#include <cstdint>

#define K_DIM 1024
#define N_DIM 1024
#define M_DIM 65536
#define BM 128
#define BN 128
#define BK 64
#define KSTAGES (K_DIM / BK)        // 16
#define PIPE 3
#define THREADS 160                  // 4 consumer warps + 1 producer warp
#define CONS_THREADS 128
#define GRID 304                     // persistent: 2 CTAs/SM (GB300, 152 SMs)
#define NTILES ((M_DIM / BM) * (N_DIM / BN))   // 4096
#define PITCH 144                    // 128B data + 16B pad (conflict-free ldmatrix)
#define A_OFF 0
#define A_BYTES (BM * PITCH)         // 18432
#define B_OFF A_BYTES
#define B_BYTES (BN * PITCH)         // 18432
#define STAGE_BYTES (A_BYTES + B_BYTES)   // 36864
#define MBAR_OFF (PIPE * STAGE_BYTES)     // 110592
#define SMEM_TOTAL (MBAR_OFF + 128)       // 110720 (x2 CTAs = 221440)

// ---- device-global scratch (allocation-free) ----
__device__ float g_partial[1024];
__device__ float g_scale;
__device__ __align__(256) __half g_wq[N_DIM * K_DIM];         // ternary W, fp16
__device__ __align__(256) __half g_xh[(size_t)M_DIM * K_DIM]; // X in fp16

__device__ __forceinline__ uint32_t smem_u32(const void* p) {
    uint32_t a;
    asm("{ .reg .u64 t; cvta.to.shared.u64 t, %1; cvt.u32.u64 %0, t; }"
        : "=r"(a) : "l"(p));
    return a;
}
__device__ __forceinline__ void cp16(uint32_t dst, const void* src) {
    asm volatile("cp.async.cg.shared.global [%0], [%1], 16;" :: "r"(dst), "l"(src));
}
__device__ __forceinline__ void mbar_init(uint32_t bar, uint32_t cnt) {
    asm volatile("mbarrier.init.shared.b64 [%0], %1;" :: "r"(bar), "r"(cnt) : "memory");
}
__device__ __forceinline__ void mbar_arrive(uint32_t bar) {
    asm volatile("mbarrier.arrive.release.cta.shared.b64 _, [%0];" :: "r"(bar) : "memory");
}
__device__ __forceinline__ void cp_arrive_noinc(uint32_t bar) {
    asm volatile("cp.async.mbarrier.arrive.noinc.shared.b64 [%0];" :: "r"(bar) : "memory");
}
__device__ __forceinline__ void wait_parity(uint32_t bar, uint32_t phase) {
    asm volatile(
        "{\n\t.reg .pred P;\n"
        "W_%=:\n\t"
        "mbarrier.try_wait.parity.acquire.cta.shared::cta.b64 P, [%0], %1, 0x989680;\n\t"
        "@P bra.uni D_%=;\n\t"
        "bra.uni W_%=;\n\t"
        "D_%=:\n\t}"
        :: "r"(bar), "r"(phase) : "memory");
}
__device__ __forceinline__ void ldsm_x4(uint32_t* r, uint32_t addr) {
    asm volatile("ldmatrix.sync.aligned.m8n8.x4.shared.b16 {%0,%1,%2,%3}, [%4];"
                 : "=r"(r[0]), "=r"(r[1]), "=r"(r[2]), "=r"(r[3]) : "r"(addr));
}
__device__ __forceinline__ void mma16816(float* c, const uint32_t* a, uint32_t b0, uint32_t b1) {
    asm volatile(
        "mma.sync.aligned.m16n8k16.row.col.f32.f16.f16.f32 "
        "{%0,%1,%2,%3}, {%4,%5,%6,%7}, {%8,%9}, {%0,%1,%2,%3};"
        : "+f"(c[0]), "+f"(c[1]), "+f"(c[2]), "+f"(c[3])
        : "r"(a[0]), "r"(a[1]), "r"(a[2]), "r"(a[3]), "r"(b0), "r"(b1));
}

// ============================ pre-kernels ============================

__global__ void k_absmean(const float* __restrict__ w) {
    __shared__ float red[256];
    int t = threadIdx.x;
    float4 v = *(const float4*)(w + (size_t)blockIdx.x * 1024 + t * 4);
    red[t] = fabsf(v.x) + fabsf(v.y) + fabsf(v.z) + fabsf(v.w);
    __syncthreads();
    for (int o = 128; o > 0; o >>= 1) {
        if (t < o) red[t] += red[t + o];
        __syncthreads();
    }
    if (t == 0) g_partial[blockIdx.x] = red[0];
}

__global__ void k_scale() {
    __shared__ float red[256];
    int t = threadIdx.x;
    red[t] = g_partial[t] + g_partial[t + 256] + g_partial[t + 512] + g_partial[t + 768];
    __syncthreads();
    for (int o = 128; o > 0; o >>= 1) {
        if (t < o) red[t] += red[t + o];
        __syncthreads();
    }
    if (t == 0) g_scale = fmaxf(red[0] / 1048576.0f, 1e-5f);
}

__global__ void k_quant(const float* __restrict__ w) {
    int i = (blockIdx.x * 256 + threadIdx.x) * 4;
    float s = g_scale;
    float4 v = *(const float4*)(w + i);
    float q0 = fminf(fmaxf(rintf(v.x / s), -1.0f), 1.0f);
    float q1 = fminf(fmaxf(rintf(v.y / s), -1.0f), 1.0f);
    float q2 = fminf(fmaxf(rintf(v.z / s), -1.0f), 1.0f);
    float q3 = fminf(fmaxf(rintf(v.w / s), -1.0f), 1.0f);
    __half2 h0 = __floats2half2_rn(q0, q1);
    __half2 h1 = __floats2half2_rn(q2, q3);
    uint2 u;
    u.x = *reinterpret_cast<uint32_t*>(&h0);
    u.y = *reinterpret_cast<uint32_t*>(&h1);
    *(uint2*)(g_wq + i) = u;
}

__global__ void k_xconv(const float* __restrict__ x) {
    size_t i = ((size_t)blockIdx.x * 256 + threadIdx.x) * 8;
    float4 v0 = *(const float4*)(x + i);
    float4 v1 = *(const float4*)(x + i + 4);
    __half2 h0 = __floats2half2_rn(v0.x, v0.y);
    __half2 h1 = __floats2half2_rn(v0.z, v0.w);
    __half2 h2 = __floats2half2_rn(v1.x, v1.y);
    __half2 h3 = __floats2half2_rn(v1.z, v1.w);
    uint4 u;
    u.x = *(uint32_t*)&h0; u.y = *(uint32_t*)&h1;
    u.z = *(uint32_t*)&h2; u.w = *(uint32_t*)&h3;
    *(uint4*)(g_xh + i) = u;
}

// ====== GEMM: persistent, warp-specialized, 2 CTAs/SM for stall overlap ======

__global__ void __launch_bounds__(THREADS, 2)
bitlinear_gemm(float* __restrict__ out) {
    extern __shared__ __align__(128) char smem[];
    uint32_t sb = smem_u32(smem);
    int tid = threadIdx.x, lane = tid & 31, wid = tid >> 5;
    int bid = blockIdx.x;

    uint32_t full0  = sb + MBAR_OFF;
    uint32_t empty0 = sb + MBAR_OFF + PIPE * 8;
    if (tid == 0) {
        #pragma unroll
        for (int i = 0; i < PIPE; i++) {
            mbar_init(full0 + i * 8, 32);      // 32 producer threads (noinc)
            mbar_init(empty0 + i * 8, 128);    // 128 consumer threads
        }
    }
    __syncthreads();

    if (wid == 4) {
        // ============ PRODUCER (1 warp, 32 threads): A + B via cp.async =======
        int prow = lane >> 3, pcol = lane & 7;   // 4 rows x 8 col16 per pass
        uint32_t adst = sb + A_OFF + prow * PITCH + pcol * 16;
        uint32_t bdst = sb + B_OFF + prow * PITCH + pcol * 16;

        int pb = 0, pph = 1;
        #pragma unroll 1
        for (int t = bid; t < NTILES; t += GRID) {
            int m0 = (t >> 3) * BM, n0 = (t & 7) * BN;
            const __half* abase = g_xh + (size_t)(m0 + prow) * K_DIM + pcol * 8;
            const __half* bbase = g_wq + (size_t)(n0 + prow) * K_DIM + pcol * 8;
            #pragma unroll 1
            for (int s = 0; s < KSTAGES; s++) {
                wait_parity(empty0 + pb * 8, pph);
                uint32_t ab = pb * STAGE_BYTES;
                int k0 = s * BK;
                #pragma unroll
                for (int i = 0; i < 32; i++)      // A: 128 rows, 4/pass
                    cp16(adst + ab + i * 4 * PITCH, abase + (size_t)i * 4 * K_DIM + k0);
                #pragma unroll
                for (int i = 0; i < 32; i++)      // B: 128 rows, 4/pass
                    cp16(bdst + ab + i * 4 * PITCH, bbase + (size_t)i * 4 * K_DIM + k0);
                cp_arrive_noinc(full0 + pb * 8);
                if (++pb == PIPE) { pb = 0; pph ^= 1; }
            }
        }
    } else {
        // ======================= CONSUMER (4 warps, 2x2) ======================
        int wm = wid & 1, wn = (wid >> 1) & 1;   // 64x64 warp tiles
        uint32_t a_ld[4], b_ld[4];
        #pragma unroll
        for (int mt = 0; mt < 4; mt++)
            a_ld[mt] = sb + A_OFF + (wm * 64 + mt * 16 + (lane & 15)) * PITCH
                     + (lane >> 4) * 16;
        #pragma unroll
        for (int np = 0; np < 4; np++)
            b_ld[np] = sb + B_OFF
                     + (wn * 64 + np * 16 + (lane & 7) + ((lane >> 4) & 1) * 8) * PITCH
                     + ((lane >> 3) & 1) * 16;

        float acc[4][8][4];
        #pragma unroll
        for (int i = 0; i < 4; i++)
            #pragma unroll
            for (int j = 0; j < 8; j++)
                #pragma unroll
                for (int k = 0; k < 4; k++) acc[i][j][k] = 0.0f;

        float sc = g_scale;
        int cb = 0, cph = 0;
        #pragma unroll 1
        for (int t = bid; t < NTILES; t += GRID) {
            #pragma unroll 1
            for (int s = 0; s < KSTAGES; s++) {
                wait_parity(full0 + cb * 8, cph);
                uint32_t ab = cb * STAGE_BYTES;
                #pragma unroll
                for (int ks = 0; ks < 4; ks++) {
                    uint32_t a[4][4], b[4][4];
                    #pragma unroll
                    for (int mt = 0; mt < 4; mt++)
                        ldsm_x4(a[mt], a_ld[mt] + ab + ks * 32);
                    #pragma unroll
                    for (int np = 0; np < 4; np++)
                        ldsm_x4(b[np], b_ld[np] + ab + ks * 32);
                    #pragma unroll
                    for (int np = 0; np < 4; np++) {
                        #pragma unroll
                        for (int mt = 0; mt < 4; mt++) {
                            mma16816(acc[mt][2 * np],     a[mt], b[np][0], b[np][1]);
                            mma16816(acc[mt][2 * np + 1], a[mt], b[np][2], b[np][3]);
                        }
                    }
                }
                mbar_arrive(empty0 + cb * 8);
                if (++cb == PIPE) { cb = 0; cph ^= 1; }
            }

            // epilogue for tile t
            int m0 = (t >> 3) * BM, n0 = (t & 7) * BN;
            int row_base = m0 + wm * 64 + (lane >> 2);
            int col_base = n0 + wn * 64 + (lane & 3) * 2;
            #pragma unroll
            for (int mt = 0; mt < 4; mt++) {
                #pragma unroll
                for (int nt = 0; nt < 8; nt++) {
                    float2 v0, v1;
                    v0.x = acc[mt][nt][0] * sc; v0.y = acc[mt][nt][1] * sc;
                    v1.x = acc[mt][nt][2] * sc; v1.y = acc[mt][nt][3] * sc;
                    acc[mt][nt][0] = 0.0f; acc[mt][nt][1] = 0.0f;
                    acc[mt][nt][2] = 0.0f; acc[mt][nt][3] = 0.0f;
                    size_t r0 = (size_t)(row_base + mt * 16) * N_DIM + col_base + nt * 8;
                    size_t r1 = r0 + 8 * N_DIM;
                    *(float2*)(out + r0) = v0;
                    *(float2*)(out + r1) = v1;
                }
            }
        }
    }
}

// ============================ launch ============================

extern "C" void kernel_launch(void* const* d_in, const int* in_sizes, int n_in,
                              void* d_out, int out_size) {
    const float* x = (const float*)d_in[0];
    const float* w = (const float*)d_in[1];
    float* out = (float*)d_out;
    int M = in_sizes[0] / K_DIM;   // 65536

    cudaFuncSetAttribute(bitlinear_gemm,
                         cudaFuncAttributeMaxDynamicSharedMemorySize, SMEM_TOTAL);

    k_absmean<<<1024, 256>>>(w);
    k_scale<<<1, 256>>>();
    k_quant<<<1024, 256>>>(w);
    k_xconv<<<(int)(((size_t)M * K_DIM) / (256 * 8)), 256>>>(x);

    bitlinear_gemm<<<GRID, THREADS, SMEM_TOTAL>>>(out);
}

// round 10
// speedup vs baseline: 1.0410x; 1.0066x over previous
#include <cuda_runtime.h>
#include <cuda_fp16.h>
#include <cstdint>

#define K_DIM 1024
#define N_DIM 1024
#define M_DIM 65536
#define BM 128
#define BN 256
#define BK 64
#define KSTAGES (K_DIM / BK)        // 16
#define PIPE 4
#define THREADS 320                  // 8 consumer warps + 2 producer warps
#define CONS_THREADS 256
#define GRID 152                     // persistent: 1 CTA/SM (GB300)
#define NTILES ((M_DIM / BM) * (N_DIM / BN))   // 2048
#define PITCH 144                    // 128B data + 16B pad (conflict-free ldmatrix)
#define A_OFF 0
#define A_BYTES (BM * PITCH)         // 18432
#define B_OFF A_BYTES
#define B_BYTES (BN * PITCH)         // 36864
#define STAGE_BYTES (A_BYTES + B_BYTES)   // 55296
#define MBAR_OFF (PIPE * STAGE_BYTES)     // 221184
#define SMEM_TOTAL (MBAR_OFF + 128)

// ---- device-global scratch (allocation-free) ----
__device__ float g_partial[1024];
__device__ float g_scale;
__device__ __align__(256) __half g_wq[N_DIM * K_DIM];         // ternary W, fp16
__device__ __align__(256) __half g_xh[(size_t)M_DIM * K_DIM]; // X in fp16

__device__ __forceinline__ uint32_t smem_u32(const void* p) {
    uint32_t a;
    asm("{ .reg .u64 t; cvta.to.shared.u64 t, %1; cvt.u32.u64 %0, t; }"
        : "=r"(a) : "l"(p));
    return a;
}
__device__ __forceinline__ void cp16(uint32_t dst, const void* src) {
    asm volatile("cp.async.cg.shared.global [%0], [%1], 16;" :: "r"(dst), "l"(src));
}
__device__ __forceinline__ void mbar_init(uint32_t bar, uint32_t cnt) {
    asm volatile("mbarrier.init.shared.b64 [%0], %1;" :: "r"(bar), "r"(cnt) : "memory");
}
__device__ __forceinline__ void mbar_arrive(uint32_t bar) {
    asm volatile("mbarrier.arrive.release.cta.shared.b64 _, [%0];" :: "r"(bar) : "memory");
}
__device__ __forceinline__ void cp_arrive_noinc(uint32_t bar) {
    asm volatile("cp.async.mbarrier.arrive.noinc.shared.b64 [%0];" :: "r"(bar) : "memory");
}
__device__ __forceinline__ void wait_parity(uint32_t bar, uint32_t phase) {
    asm volatile(
        "{\n\t.reg .pred P;\n"
        "W_%=:\n\t"
        "mbarrier.try_wait.parity.acquire.cta.shared::cta.b64 P, [%0], %1, 0x989680;\n\t"
        "@P bra.uni D_%=;\n\t"
        "bra.uni W_%=;\n\t"
        "D_%=:\n\t}"
        :: "r"(bar), "r"(phase) : "memory");
}
__device__ __forceinline__ void ldsm_x4(uint32_t* r, uint32_t addr) {
    asm volatile("ldmatrix.sync.aligned.m8n8.x4.shared.b16 {%0,%1,%2,%3}, [%4];"
                 : "=r"(r[0]), "=r"(r[1]), "=r"(r[2]), "=r"(r[3]) : "r"(addr));
}
__device__ __forceinline__ void mma16816(float* c, const uint32_t* a, uint32_t b0, uint32_t b1) {
    asm volatile(
        "mma.sync.aligned.m16n8k16.row.col.f32.f16.f16.f32 "
        "{%0,%1,%2,%3}, {%4,%5,%6,%7}, {%8,%9}, {%0,%1,%2,%3};"
        : "+f"(c[0]), "+f"(c[1]), "+f"(c[2]), "+f"(c[3])
        : "r"(a[0]), "r"(a[1]), "r"(a[2]), "r"(a[3]), "r"(b0), "r"(b1));
}

// ============================ pre-kernels ============================

__global__ void k_absmean(const float* __restrict__ w) {
    __shared__ float red[256];
    int t = threadIdx.x;
    float4 v = *(const float4*)(w + (size_t)blockIdx.x * 1024 + t * 4);
    red[t] = fabsf(v.x) + fabsf(v.y) + fabsf(v.z) + fabsf(v.w);
    __syncthreads();
    for (int o = 128; o > 0; o >>= 1) {
        if (t < o) red[t] += red[t + o];
        __syncthreads();
    }
    if (t == 0) g_partial[blockIdx.x] = red[0];
}

__global__ void k_scale() {
    __shared__ float red[256];
    int t = threadIdx.x;
    red[t] = g_partial[t] + g_partial[t + 256] + g_partial[t + 512] + g_partial[t + 768];
    __syncthreads();
    for (int o = 128; o > 0; o >>= 1) {
        if (t < o) red[t] += red[t + o];
        __syncthreads();
    }
    if (t == 0) g_scale = fmaxf(red[0] / 1048576.0f, 1e-5f);
}

__global__ void k_quant(const float* __restrict__ w) {
    int i = (blockIdx.x * 256 + threadIdx.x) * 4;
    float s = g_scale;
    float4 v = *(const float4*)(w + i);
    float q0 = fminf(fmaxf(rintf(v.x / s), -1.0f), 1.0f);
    float q1 = fminf(fmaxf(rintf(v.y / s), -1.0f), 1.0f);
    float q2 = fminf(fmaxf(rintf(v.z / s), -1.0f), 1.0f);
    float q3 = fminf(fmaxf(rintf(v.w / s), -1.0f), 1.0f);
    __half2 h0 = __floats2half2_rn(q0, q1);
    __half2 h1 = __floats2half2_rn(q2, q3);
    uint2 u;
    u.x = *reinterpret_cast<uint32_t*>(&h0);
    u.y = *reinterpret_cast<uint32_t*>(&h1);
    *(uint2*)(g_wq + i) = u;
}

__global__ void k_xconv(const float* __restrict__ x) {
    size_t i = ((size_t)blockIdx.x * 256 + threadIdx.x) * 8;
    float4 v0 = *(const float4*)(x + i);
    float4 v1 = *(const float4*)(x + i + 4);
    __half2 h0 = __floats2half2_rn(v0.x, v0.y);
    __half2 h1 = __floats2half2_rn(v0.z, v0.w);
    __half2 h2 = __floats2half2_rn(v1.x, v1.y);
    __half2 h3 = __floats2half2_rn(v1.z, v1.w);
    uint4 u;
    u.x = *(uint32_t*)&h0; u.y = *(uint32_t*)&h1;
    u.z = *(uint32_t*)&h2; u.w = *(uint32_t*)&h3;
    *(uint4*)(g_xh + i) = u;
}

// ====== GEMM: persistent, warp-specialized, reg-pipelined fragments ==========

__global__ void __launch_bounds__(THREADS, 1)
bitlinear_gemm(float* __restrict__ out) {
    extern __shared__ __align__(128) char smem[];
    uint32_t sb = smem_u32(smem);
    int tid = threadIdx.x, lane = tid & 31, wid = tid >> 5;
    int bid = blockIdx.x;

    uint32_t full0  = sb + MBAR_OFF;
    uint32_t empty0 = sb + MBAR_OFF + PIPE * 8;
    if (tid == 0) {
        #pragma unroll
        for (int i = 0; i < PIPE; i++) {
            mbar_init(full0 + i * 8, 64);      // 64 producer threads (noinc)
            mbar_init(empty0 + i * 8, 256);    // 256 consumer threads
        }
    }
    __syncthreads();

    if (wid >= 8) {
        // ============ PRODUCER (2 warps, 64 threads): all cp.async ============
        int ptid = tid - CONS_THREADS;          // 0..63
        int prow = ptid >> 3, pcol = ptid & 7;  // 8 rows x 8 col16 per pass
        uint32_t adst = sb + A_OFF + prow * PITCH + pcol * 16;
        uint32_t bdst = sb + B_OFF + prow * PITCH + pcol * 16;

        int pb = 0, pph = 1;
        #pragma unroll 1
        for (int t = bid; t < NTILES; t += GRID) {
            int m0 = (t >> 2) * BM, n0 = (t & 3) * BN;
            const __half* abase = g_xh + (size_t)(m0 + prow) * K_DIM + pcol * 8;
            const __half* bbase = g_wq + (size_t)(n0 + prow) * K_DIM + pcol * 8;
            #pragma unroll 1
            for (int s = 0; s < KSTAGES; s++) {
                wait_parity(empty0 + pb * 8, pph);
                uint32_t ab = pb * STAGE_BYTES;
                int k0 = s * BK;
                #pragma unroll
                for (int i = 0; i < 16; i++)      // A: 128 rows
                    cp16(adst + ab + i * 8 * PITCH, abase + (size_t)i * 8 * K_DIM + k0);
                #pragma unroll
                for (int i = 0; i < 32; i++)      // B: 256 rows
                    cp16(bdst + ab + i * 8 * PITCH, bbase + (size_t)i * 8 * K_DIM + k0);
                cp_arrive_noinc(full0 + pb * 8);
                if (++pb == PIPE) { pb = 0; pph ^= 1; }
            }
        }
    } else {
        // ========== CONSUMER (8 warps): register-pipelined ldsm/mma ===========
        int wm = wid & 1, wn = wid >> 1;         // 2 x 4 grid, 64x64 warp tiles
        uint32_t a_ld[4], b_ld[4];
        #pragma unroll
        for (int mt = 0; mt < 4; mt++)
            a_ld[mt] = sb + A_OFF + (wm * 64 + mt * 16 + (lane & 15)) * PITCH
                     + (lane >> 4) * 16;
        #pragma unroll
        for (int np = 0; np < 4; np++)
            b_ld[np] = sb + B_OFF
                     + (wn * 64 + np * 16 + (lane & 7) + ((lane >> 4) & 1) * 8) * PITCH
                     + ((lane >> 3) & 1) * 16;

        float acc[4][8][4];
        #pragma unroll
        for (int i = 0; i < 4; i++)
            #pragma unroll
            for (int j = 0; j < 8; j++)
                #pragma unroll
                for (int k = 0; k < 4; k++) acc[i][j][k] = 0.0f;

        float sc = g_scale;
        int cb = 0, cph = 0;
        #pragma unroll 1
        for (int t = bid; t < NTILES; t += GRID) {
            #pragma unroll 1
            for (int s = 0; s < KSTAGES; s++) {
                wait_parity(full0 + cb * 8, cph);
                uint32_t ab = cb * STAGE_BYTES;

                // double-buffered fragments: a[2] per-ks, b[2] per-np-slot
                uint32_t a[2][4][4], b[2][4];

                // preamble: a of ks0, b of (ks0, np0)
                #pragma unroll
                for (int mt = 0; mt < 4; mt++) ldsm_x4(a[0][mt], a_ld[mt] + ab);
                ldsm_x4(b[0], b_ld[0] + ab);

                #pragma unroll
                for (int ks = 0; ks < 4; ks++) {
                    int ac = ks & 1;
                    #pragma unroll
                    for (int np = 0; np < 4; np++) {
                        int slot = ks * 4 + np;
                        int bc = slot & 1, bn = bc ^ 1;
                        // prefetch next slot's fragments
                        if (np < 3) {
                            ldsm_x4(b[bn], b_ld[np + 1] + ab + ks * 32);
                        } else if (ks < 3) {
                            #pragma unroll
                            for (int mt = 0; mt < 4; mt++)
                                ldsm_x4(a[ac ^ 1][mt], a_ld[mt] + ab + (ks + 1) * 32);
                            ldsm_x4(b[bn], b_ld[0] + ab + (ks + 1) * 32);
                        }
                        // 8 mma on current fragments
                        #pragma unroll
                        for (int mt = 0; mt < 4; mt++) {
                            mma16816(acc[mt][2 * np],     a[ac][mt], b[bc][0], b[bc][1]);
                            mma16816(acc[mt][2 * np + 1], a[ac][mt], b[bc][2], b[bc][3]);
                        }
                    }
                }
                mbar_arrive(empty0 + cb * 8);
                if (++cb == PIPE) { cb = 0; cph ^= 1; }
            }

            // epilogue for tile t (producers keep streaming meanwhile)
            int m0 = (t >> 2) * BM, n0 = (t & 3) * BN;
            int row_base = m0 + wm * 64 + (lane >> 2);
            int col_base = n0 + wn * 64 + (lane & 3) * 2;
            #pragma unroll
            for (int mt = 0; mt < 4; mt++) {
                #pragma unroll
                for (int nt = 0; nt < 8; nt++) {
                    float2 v0, v1;
                    v0.x = acc[mt][nt][0] * sc; v0.y = acc[mt][nt][1] * sc;
                    v1.x = acc[mt][nt][2] * sc; v1.y = acc[mt][nt][3] * sc;
                    acc[mt][nt][0] = 0.0f; acc[mt][nt][1] = 0.0f;
                    acc[mt][nt][2] = 0.0f; acc[mt][nt][3] = 0.0f;
                    size_t r0 = (size_t)(row_base + mt * 16) * N_DIM + col_base + nt * 8;
                    size_t r1 = r0 + 8 * N_DIM;
                    *(float2*)(out + r0) = v0;
                    *(float2*)(out + r1) = v1;
                }
            }
        }
    }
}

// ============================ launch ============================

extern "C" void kernel_launch(void* const* d_in, const int* in_sizes, int n_in,
                              void* d_out, int out_size) {
    const float* x = (const float*)d_in[0];
    const float* w = (const float*)d_in[1];
    float* out = (float*)d_out;
    int M = in_sizes[0] / K_DIM;   // 65536

    cudaFuncSetAttribute(bitlinear_gemm,
                         cudaFuncAttributeMaxDynamicSharedMemorySize, SMEM_TOTAL);

    k_absmean<<<1024, 256>>>(w);
    k_scale<<<1, 256>>>();
    k_quant<<<1024, 256>>>(w);
    k_xconv<<<(int)(((size_t)M * K_DIM) / (256 * 8)), 256>>>(x);

    bitlinear_gemm<<<GRID, THREADS, SMEM_TOTAL>>>(out);
}